// round 1
// baseline (speedup 1.0000x reference)
#include <cuda_runtime.h>
#include <cuda_bf16.h>

// Scalar accumulator in device global (no allocations allowed).
static __device__ double g_accum;

__global__ void wmse_zero_kernel() {
    g_accum = 0.0;
}

__global__ void __launch_bounds__(256, 8)
wmse_reduce_kernel(const float4* __restrict__ pred4,
                   const int4*   __restrict__ lab4,
                   const float*  __restrict__ weights,
                   long long nv4) {
    __shared__ float sw[16];
    if (threadIdx.x < 10) sw[threadIdx.x] = weights[threadIdx.x];
    __syncthreads();

    float acc = 0.0f;
    long long stride = (long long)gridDim.x * blockDim.x;
    for (long long i = (long long)blockIdx.x * blockDim.x + threadIdx.x;
         i < nv4; i += stride) {
        float4 p = pred4[i];
        int4   l = lab4[i];
        float d0 = p.x - (float)l.x;
        float d1 = p.y - (float)l.y;
        float d2 = p.z - (float)l.z;
        float d3 = p.w - (float)l.w;
        acc = fmaf(sw[l.x] * d0, d0, acc);
        acc = fmaf(sw[l.y] * d1, d1, acc);
        acc = fmaf(sw[l.z] * d2, d2, acc);
        acc = fmaf(sw[l.w] * d3, d3, acc);
    }

    // warp reduction
    #pragma unroll
    for (int o = 16; o > 0; o >>= 1)
        acc += __shfl_xor_sync(0xFFFFFFFFu, acc, o);

    __shared__ float warpsum[8];
    int lane = threadIdx.x & 31;
    int wid  = threadIdx.x >> 5;
    if (lane == 0) warpsum[wid] = acc;
    __syncthreads();

    if (wid == 0) {
        float v = (lane < 8) ? warpsum[lane] : 0.0f;
        #pragma unroll
        for (int o = 4; o > 0; o >>= 1)
            v += __shfl_xor_sync(0xFFFFFFFFu, v, o);
        if (lane == 0)
            atomicAdd(&g_accum, (double)v);
    }
}

__global__ void wmse_finalize_kernel(float* out, long long n) {
    *out = (float)(g_accum / (double)n);
}

extern "C" void kernel_launch(void* const* d_in, const int* in_sizes, int n_in,
                              void* d_out, int out_size) {
    const float* pred    = (const float*)d_in[0];
    const int*   labels  = (const int*)d_in[1];
    const float* weights = (const float*)d_in[2];
    float* out = (float*)d_out;

    long long n   = (long long)in_sizes[0];
    long long nv4 = n >> 2;   // N = 2^25, divisible by 4

    wmse_zero_kernel<<<1, 1>>>();

    const int threads = 256;
    int blocks = 148 * 16;  // 2368 blocks -> ~14 vec4 iters/thread, deep MLP
    long long needed = (nv4 + threads - 1) / threads;
    if ((long long)blocks > needed) blocks = (int)needed;

    wmse_reduce_kernel<<<blocks, threads>>>(
        (const float4*)pred, (const int4*)labels, weights, nv4);

    wmse_finalize_kernel<<<1, 1>>>(out, n);
}